// round 1
// baseline (speedup 1.0000x reference)
#include <cuda_runtime.h>
#include <cuda_bf16.h>
#include <cstdint>

// Problem constants (fixed by the dataset)
#define BB  16
#define TT  128   // txt_T
#define MM  512   // mel_T
#define NC  80    // N_MEL

// Tiling for the log-prob kernel
#define TBLK 32
#define MBLK 128
#define K1_THREADS 256

// Scratch (no cudaMalloc allowed)
__device__ float g_elp[(size_t)BB * MM * TT];   // exp(lp), layout [b][m][t]
__device__ float g_alpha[BB];                   // per-batch alpha_last / mel_len

// Dynamic smem layout
//   xs : float2[NC][MBLK]      (x, x^2)         = 81920 B
//   wa : float2[TBLK][81]      (w, a), padded   = 20736 B
//   kp : float [TBLK][8]                        =  1024 B
//   kc : float [TBLK]                           =   128 B
#define SM_XS_OFF 0
#define SM_WA_OFF (NC * MBLK * 8)
#define SM_KP_OFF (SM_WA_OFF + TBLK * 81 * 8)
#define SM_KC_OFF (SM_KP_OFF + TBLK * 8 * 4)
#define SM_TOTAL  (SM_KC_OFF + TBLK * 4)

// ---------------------------------------------------------------------------
// Kernel 1: log_prob_matrix + exp(log_prob) scratch
//   lp[b,t,m] = -(1/160) * ( sum_c w*x^2 + sum_c a*x + kconst )
//   w = exp(-lv), a = -2*w*mu, kconst = sum_c (w*mu^2 + lv)
// Grid: (MM/MBLK, TT/TBLK, BB) = (4,4,16), 256 threads.
// ---------------------------------------------------------------------------
__global__ __launch_bounds__(K1_THREADS)
void k_logprob(const float* __restrict__ ml,     // [B, TT, 2*NC]
               const float* __restrict__ mel,    // [B, NC, MM]
               float* __restrict__ lpm)          // [B, TT, MM] (d_out + 1)
{
    extern __shared__ char smraw[];
    float2* xs = (float2*)(smraw + SM_XS_OFF);   // [NC][MBLK]
    float2* wa = (float2*)(smraw + SM_WA_OFF);   // [TBLK][81]
    float*  kp = (float*) (smraw + SM_KP_OFF);   // [TBLK][8]
    float*  kc = (float*) (smraw + SM_KC_OFF);   // [TBLK]

    const int b  = blockIdx.z;
    const int t0 = blockIdx.y * TBLK;
    const int m0 = blockIdx.x * MBLK;
    const int tid = threadIdx.x;

    // Phase A: coefficients for 32 t-rows. thread -> (t = tid/8, c-lane = tid%8)
    {
        const int t  = tid >> 3;        // 0..31
        const int cl = tid & 7;         // 0..7
        const float* row = ml + ((size_t)(b * TT + t0 + t)) * (2 * NC);
        float kpart = 0.f;
#pragma unroll
        for (int i = 0; i < 10; i++) {
            int c = cl + 8 * i;
            float mu = row[c];
            float lv = row[NC + c];
            float w  = __expf(-lv);
            float a  = -2.f * w * mu;
            wa[t * 81 + c] = make_float2(w, a);
            kpart += w * mu * mu + lv;
        }
        kp[t * 8 + cl] = kpart;
    }

    // Phase B: melspec tile (x, x^2)
    for (int lin = tid; lin < NC * MBLK; lin += K1_THREADS) {
        int c  = lin / MBLK;
        int mc = lin % MBLK;
        float x = mel[((size_t)(b * NC + c)) * MM + m0 + mc];
        xs[c * MBLK + mc] = make_float2(x, x * x);
    }
    __syncthreads();

    if (tid < TBLK) {
        float s = 0.f;
#pragma unroll
        for (int i = 0; i < 8; i++) s += kp[tid * 8 + i];
        kc[tid] = s;
    }
    __syncthreads();

    // Phase C: register micro-tile 2t x 8m per thread
    const int tx = tid & 15;     // m lane
    const int ty = tid >> 4;     // t pair index: t_local = 2*ty + {0,1}
    float acc0[8], acc1[8];
#pragma unroll
    for (int j = 0; j < 8; j++) { acc0[j] = 0.f; acc1[j] = 0.f; }

#pragma unroll 4
    for (int c = 0; c < NC; c++) {
        float2 w0 = wa[(2 * ty + 0) * 81 + c];
        float2 w1 = wa[(2 * ty + 1) * 81 + c];
#pragma unroll
        for (int j = 0; j < 8; j++) {
            float2 xv = xs[c * MBLK + tx + 16 * j];
            acc0[j] += w0.x * xv.y + w0.y * xv.x;
            acc1[j] += w1.x * xv.y + w1.y * xv.x;
        }
    }

    const float k0 = kc[2 * ty + 0];
    const float k1 = kc[2 * ty + 1];
    const int ta = t0 + 2 * ty;
#pragma unroll
    for (int j = 0; j < 8; j++) {
        int m = m0 + tx + 16 * j;
        float lp0 = -(acc0[j] + k0) * (1.f / (2.f * NC));
        float lp1 = -(acc1[j] + k1) * (1.f / (2.f * NC));
        lpm[((size_t)(b * TT + ta + 0)) * MM + m] = lp0;
        lpm[((size_t)(b * TT + ta + 1)) * MM + m] = lp1;
        g_elp[((size_t)b * MM + m) * TT + (ta + 0)] = __expf(lp0);
        g_elp[((size_t)b * MM + m) * TT + (ta + 1)] = __expf(lp1);
    }
}

// ---------------------------------------------------------------------------
// Kernel 2: forward scan in probability domain, one warp per batch.
// Lane holds t = 4*lane + {0..3}. Recurrence:
//   q[j] <- (q[j] + q[j-1]) * exp(lp[b, j, m])
// Exact power-of-2 rescale every 16 steps (warp max -> exponent field).
// ---------------------------------------------------------------------------
__global__ __launch_bounds__(32)
void k_scan(const float* __restrict__ lpm,      // d_out + 1
            const int* __restrict__ tlen,
            const int* __restrict__ mlen)
{
    const int b    = blockIdx.x;
    const int lane = threadIdx.x;
    const float4* __restrict__ Ev =
        (const float4*)(g_elp + (size_t)b * MM * TT);   // [m][32] float4

    const int mel_len = mlen[b];
    const int txt_len = tlen[b];
    const int last = mel_len - 1;

    float q0 = (lane == 0) ? 1.f : 0.f;
    float q1 = 0.f, q2 = 0.f, q3 = 0.f;
    const float L0 = lpm[(size_t)b * TT * MM];   // lp[b,0,0]
    int kTot = 0;

    // prefetch ring, depth 16
    float4 pf[16];
#pragma unroll
    for (int i = 0; i < 16; i++) {
        int m = 1 + i; if (m > MM - 1) m = MM - 1;
        pf[i] = Ev[(size_t)m * 32 + lane];
    }

    if (last >= 1) {
        for (int m0 = 1; m0 <= last; m0 += 16) {
#pragma unroll
            for (int i = 0; i < 16; i++) {
                int m = m0 + i;
                float4 e = pf[i];
                int mn = m + 16; if (mn > MM - 1) mn = MM - 1;
                pf[i] = Ev[(size_t)mn * 32 + lane];

                float top = __shfl_up_sync(0xffffffffu, q3, 1);
                if (lane == 0) top = 0.f;
                float n0 = (q0 + top) * e.x;
                float n1 = (q1 + q0)  * e.y;
                float n2 = (q2 + q1)  * e.z;
                float n3 = (q3 + q2)  * e.w;
                q0 = n0; q1 = n1; q2 = n2; q3 = n3;
                if (m == last) goto done;
            }
            // rescale: exact *2^k
            {
                float s = fmaxf(fmaxf(q0, q1), fmaxf(q2, q3));
#pragma unroll
                for (int o = 16; o; o >>= 1)
                    s = fmaxf(s, __shfl_xor_sync(0xffffffffu, s, o));
                if (s > 0.f) {
                    int eb = (__float_as_int(s) >> 23) & 0xff;
                    float sc = __int_as_float((254 - eb) << 23);
                    q0 *= sc; q1 *= sc; q2 *= sc; q3 *= sc;
                    kTot += eb - 127;
                }
            }
        }
    }
done:
    {
        const int idx = txt_len - 1;
        const int sel = idx & 3;
        float v = (sel == 0) ? q0 : (sel == 1) ? q1 : (sel == 2) ? q2 : q3;
        v = __shfl_sync(0xffffffffu, v, idx >> 2);
        if (lane == 0) {
            float alpha = __logf(v) + (float)kTot * 0.69314718055994531f + L0;
            g_alpha[b] = alpha / (float)mel_len;
        }
    }
}

// ---------------------------------------------------------------------------
// Kernel 3: loss = -mean(g_alpha)
// ---------------------------------------------------------------------------
__global__ __launch_bounds__(32)
void k_loss(float* __restrict__ out)
{
    float s = (threadIdx.x < BB) ? g_alpha[threadIdx.x] : 0.f;
#pragma unroll
    for (int o = 16; o; o >>= 1)
        s += __shfl_xor_sync(0xffffffffu, s, o);
    if (threadIdx.x == 0) out[0] = -s * (1.f / BB);
}

// ---------------------------------------------------------------------------
extern "C" void kernel_launch(void* const* d_in, const int* in_sizes, int n_in,
                              void* d_out, int out_size)
{
    const float* ml  = (const float*)d_in[0];   // mu_logvar [16,128,160]
    const float* mel = (const float*)d_in[1];   // melspec   [16,80,512]
    const int*   tl  = (const int*)d_in[2];     // text_lengths [16]
    const int*   mll = (const int*)d_in[3];     // mel_lengths  [16]
    float* out = (float*)d_out;                 // [0]=loss, [1..]=log_prob_matrix

    cudaFuncSetAttribute(k_logprob,
                         cudaFuncAttributeMaxDynamicSharedMemorySize, SM_TOTAL);

    k_logprob<<<dim3(MM / MBLK, TT / TBLK, BB), K1_THREADS, SM_TOTAL>>>(
        ml, mel, out + 1);
    k_scan<<<BB, 32>>>(out + 1, tl, mll);
    k_loss<<<1, 32>>>(out);
}

// round 2
// speedup vs baseline: 1.4771x; 1.4771x over previous
#include <cuda_runtime.h>
#include <cuda_bf16.h>
#include <cstdint>

// Problem constants (fixed by the dataset)
#define BB  16
#define TT  128   // txt_T
#define MM  512   // mel_T
#define NC  80    // N_MEL

// k_logprob tiling: block tile 32t x 128m, 128 threads, per-thread 4t x 8m
#define TBLK 32
#define MBLK 128
#define K1_THREADS 128

// Scratch (no cudaMalloc allowed). Pad g_elp: scan prefetch can overshoot.
__device__ __align__(16) float g_elp[(size_t)BB * MM * TT + 4096]; // exp(lp), [b][m][t]
__device__ float g_alpha[BB];
__device__ unsigned g_cnt = 0;

// smem layout (bytes)
#define SM_X2_OFF 0
#define SM_X_OFF  (NC * 64 * 8)                 // 40960
#define SM_WA_OFF (SM_X_OFF + NC * 64 * 8)      // 81920
#define SM_KP_OFF (SM_WA_OFF + TBLK * NC * 8)   // 102400
#define SM_KC_OFF (SM_KP_OFF + TBLK * 4 * 4)    // 102912
#define SM_TOTAL  (SM_KC_OFF + TBLK * 4)        // 103040

// ---- packed f32x2 helpers (sm_103a dual-fp32 pipe; PTX-only) ----
__device__ __forceinline__ void fma2(unsigned long long& d,
                                     unsigned long long a,
                                     unsigned long long b) {
    asm("fma.rn.f32x2 %0, %1, %2, %0;" : "+l"(d) : "l"(a), "l"(b));
}
__device__ __forceinline__ unsigned long long pack2(float lo, float hi) {
    unsigned long long r;
    asm("mov.b64 %0, {%1, %2};" : "=l"(r) : "f"(lo), "f"(hi));
    return r;
}
__device__ __forceinline__ float2 unpack2(unsigned long long v) {
    float lo, hi;
    asm("mov.b64 {%0, %1}, %2;" : "=f"(lo), "=f"(hi) : "l"(v));
    return make_float2(lo, hi);
}

// ---------------------------------------------------------------------------
// Kernel 1: log_prob_matrix + exp(log_prob) scratch.
//   lp[b,t,m] = -(1/160) * ( sum_c w*x^2 + a*x  +  kconst )
//   w = exp(-lv), a = -2*w*mu, kconst = sum_c (w*mu^2 + lv)
// Grid (4,4,16), 128 threads, FFMA2 inner loop.
// ---------------------------------------------------------------------------
__global__ __launch_bounds__(K1_THREADS)
void k_logprob(const float* __restrict__ ml,     // [B, TT, 2*NC]
               const float* __restrict__ mel,    // [B, NC, MM]
               float* __restrict__ lpm)          // [B, TT, MM] (d_out + 1)
{
    extern __shared__ char sm[];
    unsigned long long* X2s = (unsigned long long*)(sm + SM_X2_OFF); // [NC][64]
    unsigned long long* Xs  = (unsigned long long*)(sm + SM_X_OFF);  // [NC][64]
    float2* wa = (float2*)(sm + SM_WA_OFF);  // [TBLK][NC] = {w, a}
    float*  kp = (float*) (sm + SM_KP_OFF);  // [TBLK][4]
    float*  kc = (float*) (sm + SM_KC_OFF);  // [TBLK]

    const int b   = blockIdx.z;
    const int t0  = blockIdx.y * TBLK;
    const int m0  = blockIdx.x * MBLK;
    const int tid = threadIdx.x;

    // Phase A: per-t coefficients. thread -> (t = tid/4, c-lane = tid%4)
    {
        const int t  = tid >> 2;
        const int cl = tid & 3;
        const float* row = ml + ((size_t)(b * TT + t0 + t)) * (2 * NC);
        float kpart = 0.f;
#pragma unroll
        for (int i = 0; i < 20; i++) {
            int c = cl + 4 * i;
            float mu = row[c];
            float lv = row[NC + c];
            float w  = __expf(-lv);
            float a  = -2.f * w * mu;
            wa[t * NC + c] = make_float2(w, a);
            kpart += __fmaf_rn(w * mu, mu, lv);
        }
        kp[t * 4 + cl] = kpart;
    }

    // Phase B: melspec tile -> packed (x2 pair) and (x pair)
    for (int lin = tid; lin < NC * 64; lin += K1_THREADS) {
        int c = lin >> 6;
        int p = lin & 63;
        float2 x = ((const float2*)(mel + ((size_t)(b * NC + c)) * MM + m0))[p];
        X2s[c * 64 + p] = pack2(x.x * x.x, x.y * x.y);
        Xs [c * 64 + p] = pack2(x.x, x.y);
    }
    __syncthreads();

    if (tid < TBLK) {
        kc[tid] = kp[tid*4] + kp[tid*4+1] + kp[tid*4+2] + kp[tid*4+3];
    }
    __syncthreads();

    // Phase C: FFMA2 micro-tile 4t x 4 m-pairs
    const int tx = tid & 15;     // m-pair lane
    const int ty = tid >> 4;     // t group (4 consecutive t)
    unsigned long long acc[4][4];
#pragma unroll
    for (int tt = 0; tt < 4; tt++)
#pragma unroll
        for (int j = 0; j < 4; j++) acc[tt][j] = 0ull;

#pragma unroll 2
    for (int c = 0; c < NC; c++) {
        unsigned long long x2p[4], xp[4];
#pragma unroll
        for (int j = 0; j < 4; j++) {
            x2p[j] = X2s[c * 64 + tx + 16 * j];
            xp[j]  = Xs [c * 64 + tx + 16 * j];
        }
#pragma unroll
        for (int tt = 0; tt < 4; tt++) {
            float2 wv = wa[(4 * ty + tt) * NC + c];
            unsigned long long ww = pack2(wv.x, wv.x);
            unsigned long long aa = pack2(wv.y, wv.y);
#pragma unroll
            for (int j = 0; j < 4; j++) {
                fma2(acc[tt][j], ww, x2p[j]);
                fma2(acc[tt][j], aa, xp[j]);
            }
        }
    }

    // Epilogue
    const float inv = -1.f / (2.f * NC);
    float kt[4];
#pragma unroll
    for (int tt = 0; tt < 4; tt++) kt[tt] = kc[4 * ty + tt];
    const int tg = t0 + 4 * ty;

#pragma unroll
    for (int j = 0; j < 4; j++) {
        const int me = m0 + 2 * (tx + 16 * j);   // even m
        float e0[4], e1[4];
#pragma unroll
        for (int tt = 0; tt < 4; tt++) {
            float2 v = unpack2(acc[tt][j]);
            float lp0 = (v.x + kt[tt]) * inv;
            float lp1 = (v.y + kt[tt]) * inv;
            float* dst = lpm + ((size_t)(b * TT + tg + tt)) * MM + me;
            dst[0] = lp0;          // d_out+1 is only 4B aligned: scalar stores
            dst[1] = lp1;
            e0[tt] = __expf(lp0);
            e1[tt] = __expf(lp1);
        }
        *(float4*)(g_elp + ((size_t)b * MM + me)     * TT + tg) =
            make_float4(e0[0], e0[1], e0[2], e0[3]);
        *(float4*)(g_elp + ((size_t)b * MM + me + 1) * TT + tg) =
            make_float4(e1[0], e1[1], e1[2], e1[3]);
    }
}

// ---------------------------------------------------------------------------
// Kernel 2: probability-domain forward scan, one warp per batch.
//   q[j] <- (q[j] + q[j-1]) * exp(lp[b, m, j])   (exact 2^k rescale / 16 steps)
// Statically-unrolled 32-step superchunks; 32-deep register prefetch ring.
// Folds the final loss reduction in (ticket + ordered reduce).
// ---------------------------------------------------------------------------
__device__ __forceinline__ void scan_rescale(float& q0, float& q1, float& q2,
                                             float& q3, int& kTot) {
    float s = fmaxf(fmaxf(q0, q1), fmaxf(q2, q3));
#pragma unroll
    for (int o = 16; o; o >>= 1)
        s = fmaxf(s, __shfl_xor_sync(0xffffffffu, s, o));
    if (s > 0.f) {
        int eb = (__float_as_int(s) >> 23) & 0xff;
        float sc = __int_as_float((254 - eb) << 23);
        q0 *= sc; q1 *= sc; q2 *= sc; q3 *= sc;
        kTot += eb - 127;
    }
}

__global__ __launch_bounds__(32)
void k_scan(const float* __restrict__ out_base,  // d_out (out[0]=loss, +1=lpm)
            const int* __restrict__ tlen,
            const int* __restrict__ mlen)
{
    const int b    = blockIdx.x;
    const int lane = threadIdx.x;
    const float4* __restrict__ Ev =
        (const float4*)(g_elp + (size_t)b * MM * TT);   // [m][32 lanes]

    const int mel_len = mlen[b];
    const int txt_len = tlen[b];
    const int last    = mel_len - 1;

    float q0 = (lane == 0) ? 1.f : 0.f;
    float q1 = 0.f, q2 = 0.f, q3 = 0.f;
    const float L0 = out_base[1 + (size_t)b * TT * MM];  // lp[b,0,0]
    int kTot = 0;
    const bool isL0 = (lane == 0);

    // 32-deep prefetch ring (static slots only — register indexed)
    float4 pf[32];
#pragma unroll
    for (int i = 0; i < 32; i++) {
        int m = 1 + i; if (m > MM - 1) m = MM - 1;
        pf[i] = Ev[(size_t)m * 32 + lane];
    }

    int m = 1;
    // main: full 32-step superchunks (slots 0..31 literal), rescale every 16
    while (m + 31 <= last) {
        const float4* src = Ev + (size_t)(m + 32) * 32 + lane;
#pragma unroll
        for (int i = 0; i < 32; i++) {
            float4 e = pf[i];
            pf[i] = src[(size_t)i * 32];        // prefetch m+32+i (padded array)
            float top = __shfl_up_sync(0xffffffffu, q3, 1);
            if (isL0) top = 0.f;
            float n0 = (q0 + top) * e.x;
            float n1 = (q1 + q0)  * e.y;
            float n2 = (q2 + q1)  * e.z;
            float n3 = (q3 + q2)  * e.w;
            q0 = n0; q1 = n1; q2 = n2; q3 = n3;
            if (i == 15) scan_rescale(q0, q1, q2, q3, kTot);
        }
        scan_rescale(q0, q1, q2, q3, kTot);
        m += 32;
    }

    // final (predicated) superchunk: <= 31 active steps, uniform freeze
    {
#pragma unroll
        for (int i = 0; i < 32; i++) {
            int mm = m + i;
            float4 e = pf[i];
            float top = __shfl_up_sync(0xffffffffu, q3, 1);
            if (isL0) top = 0.f;
            float n0 = (q0 + top) * e.x;
            float n1 = (q1 + q0)  * e.y;
            float n2 = (q2 + q1)  * e.z;
            float n3 = (q3 + q2)  * e.w;
            bool act = (mm <= last);
            q0 = act ? n0 : q0;
            q1 = act ? n1 : q1;
            q2 = act ? n2 : q2;
            q3 = act ? n3 : q3;
        }
    }

    // extract alpha_last
    {
        const int idx = txt_len - 1;
        const int sel = idx & 3;
        float v = (sel == 0) ? q0 : (sel == 1) ? q1 : (sel == 2) ? q2 : q3;
        v = __shfl_sync(0xffffffffu, v, idx >> 2);
        if (lane == 0) {
            float alpha = __logf(v) + (float)kTot * 0.69314718055994531f + L0;
            g_alpha[b] = alpha / (float)mel_len;
            __threadfence();
            unsigned ticket = atomicAdd(&g_cnt, 1u);
            if (ticket == BB - 1) {
                __threadfence();
                float s = 0.f;
#pragma unroll
                for (int i = 0; i < BB; i++)
                    s += ((volatile float*)g_alpha)[i];
                ((float*)out_base)[0] = -s * (1.f / BB);
                g_cnt = 0;   // reset for next graph replay
            }
        }
    }
}

// ---------------------------------------------------------------------------
extern "C" void kernel_launch(void* const* d_in, const int* in_sizes, int n_in,
                              void* d_out, int out_size)
{
    const float* ml  = (const float*)d_in[0];   // mu_logvar [16,128,160]
    const float* mel = (const float*)d_in[1];   // melspec   [16,80,512]
    const int*   tl  = (const int*)d_in[2];     // text_lengths [16]
    const int*   mll = (const int*)d_in[3];     // mel_lengths  [16]
    float* out = (float*)d_out;                 // [0]=loss, [1..]=log_prob_matrix

    cudaFuncSetAttribute(k_logprob,
                         cudaFuncAttributeMaxDynamicSharedMemorySize, SM_TOTAL);

    k_logprob<<<dim3(MM / MBLK, TT / TBLK, BB), K1_THREADS, SM_TOTAL>>>(
        ml, mel, out + 1);
    k_scan<<<BB, 32>>>(out, tl, mll);
}

// round 4
// speedup vs baseline: 1.4812x; 1.0027x over previous
#include <cuda_runtime.h>
#include <cuda_bf16.h>
#include <cstdint>

// Problem constants (fixed by the dataset)
#define BB  16
#define TT  128   // txt_T
#define MM  512   // mel_T
#define NC  80    // N_MEL

// k_logprob tiling: block tile 32t x 128m, 128 threads, per-thread 4t x 8m
#define TBLK 32
#define MBLK 128
#define K1_THREADS 128

// Scratch (no cudaMalloc allowed).
__device__ __align__(16) float g_elp[(size_t)BB * MM * TT + 4096]; // exp(lp), [b][m][t]
__device__ float g_alpha[BB];
__device__ unsigned g_cnt = 0;

// smem layout (bytes)
#define SM_X2_OFF 0
#define SM_X_OFF  (NC * 64 * 8)                 // 40960
#define SM_WA_OFF (SM_X_OFF + NC * 64 * 8)      // 81920
#define SM_KP_OFF (SM_WA_OFF + TBLK * NC * 8)   // 102400
#define SM_KC_OFF (SM_KP_OFF + TBLK * 4 * 4)    // 102912
#define SM_TOTAL  (SM_KC_OFF + TBLK * 4)        // 103040

// ---- packed f32x2 helpers (sm_103a dual-fp32 pipe; PTX-only) ----
__device__ __forceinline__ void fma2(unsigned long long& d,
                                     unsigned long long a,
                                     unsigned long long b) {
    asm("fma.rn.f32x2 %0, %1, %2, %0;" : "+l"(d) : "l"(a), "l"(b));
}
__device__ __forceinline__ unsigned long long pack2(float lo, float hi) {
    unsigned long long r;
    asm("mov.b64 %0, {%1, %2};" : "=l"(r) : "f"(lo), "f"(hi));
    return r;
}
__device__ __forceinline__ float2 unpack2(unsigned long long v) {
    float lo, hi;
    asm("mov.b64 {%0, %1}, %2;" : "=f"(lo), "=f"(hi) : "l"(v));
    return make_float2(lo, hi);
}

// ---------------------------------------------------------------------------
// Kernel 1: log_prob_matrix + exp(log_prob) scratch.  (unchanged, proven)
// ---------------------------------------------------------------------------
__global__ __launch_bounds__(K1_THREADS)
void k_logprob(const float* __restrict__ ml,     // [B, TT, 2*NC]
               const float* __restrict__ mel,    // [B, NC, MM]
               float* __restrict__ lpm)          // [B, TT, MM] (d_out + 1)
{
    extern __shared__ char sm[];
    unsigned long long* X2s = (unsigned long long*)(sm + SM_X2_OFF); // [NC][64]
    unsigned long long* Xs  = (unsigned long long*)(sm + SM_X_OFF);  // [NC][64]
    float2* wa = (float2*)(sm + SM_WA_OFF);  // [TBLK][NC] = {w, a}
    float*  kp = (float*) (sm + SM_KP_OFF);  // [TBLK][4]
    float*  kc = (float*) (sm + SM_KC_OFF);  // [TBLK]

    const int b   = blockIdx.z;
    const int t0  = blockIdx.y * TBLK;
    const int m0  = blockIdx.x * MBLK;
    const int tid = threadIdx.x;

    // Phase A: per-t coefficients. thread -> (t = tid/4, c-lane = tid%4)
    {
        const int t  = tid >> 2;
        const int cl = tid & 3;
        const float* row = ml + ((size_t)(b * TT + t0 + t)) * (2 * NC);
        float kpart = 0.f;
#pragma unroll
        for (int i = 0; i < 20; i++) {
            int c = cl + 4 * i;
            float mu = row[c];
            float lv = row[NC + c];
            float w  = __expf(-lv);
            float a  = -2.f * w * mu;
            wa[t * NC + c] = make_float2(w, a);
            kpart += __fmaf_rn(w * mu, mu, lv);
        }
        kp[t * 4 + cl] = kpart;
    }

    // Phase B: melspec tile -> packed (x2 pair) and (x pair)
    for (int lin = tid; lin < NC * 64; lin += K1_THREADS) {
        int c = lin >> 6;
        int p = lin & 63;
        float2 x = ((const float2*)(mel + ((size_t)(b * NC + c)) * MM + m0))[p];
        X2s[c * 64 + p] = pack2(x.x * x.x, x.y * x.y);
        Xs [c * 64 + p] = pack2(x.x, x.y);
    }
    __syncthreads();

    if (tid < TBLK) {
        kc[tid] = kp[tid*4] + kp[tid*4+1] + kp[tid*4+2] + kp[tid*4+3];
    }
    __syncthreads();

    // Phase C: FFMA2 micro-tile 4t x 4 m-pairs
    const int tx = tid & 15;     // m-pair lane
    const int ty = tid >> 4;     // t group (4 consecutive t)
    unsigned long long acc[4][4];
#pragma unroll
    for (int tt = 0; tt < 4; tt++)
#pragma unroll
        for (int j = 0; j < 4; j++) acc[tt][j] = 0ull;

#pragma unroll 2
    for (int c = 0; c < NC; c++) {
        unsigned long long x2p[4], xp[4];
#pragma unroll
        for (int j = 0; j < 4; j++) {
            x2p[j] = X2s[c * 64 + tx + 16 * j];
            xp[j]  = Xs [c * 64 + tx + 16 * j];
        }
#pragma unroll
        for (int tt = 0; tt < 4; tt++) {
            float2 wv = wa[(4 * ty + tt) * NC + c];
            unsigned long long ww = pack2(wv.x, wv.x);
            unsigned long long aa = pack2(wv.y, wv.y);
#pragma unroll
            for (int j = 0; j < 4; j++) {
                fma2(acc[tt][j], ww, x2p[j]);
                fma2(acc[tt][j], aa, xp[j]);
            }
        }
    }

    // Epilogue
    const float inv = -1.f / (2.f * NC);
    float kt[4];
#pragma unroll
    for (int tt = 0; tt < 4; tt++) kt[tt] = kc[4 * ty + tt];
    const int tg = t0 + 4 * ty;

#pragma unroll
    for (int j = 0; j < 4; j++) {
        const int me = m0 + 2 * (tx + 16 * j);   // even m
        float e0[4], e1[4];
#pragma unroll
        for (int tt = 0; tt < 4; tt++) {
            float2 v = unpack2(acc[tt][j]);
            float lp0 = (v.x + kt[tt]) * inv;
            float lp1 = (v.y + kt[tt]) * inv;
            float* dst = lpm + ((size_t)(b * TT + tg + tt)) * MM + me;
            dst[0] = lp0;          // d_out+1 is only 4B aligned: scalar stores
            dst[1] = lp1;
            e0[tt] = __expf(lp0);
            e1[tt] = __expf(lp1);
        }
        *(float4*)(g_elp + ((size_t)b * MM + me)     * TT + tg) =
            make_float4(e0[0], e0[1], e0[2], e0[3]);
        *(float4*)(g_elp + ((size_t)b * MM + me + 1) * TT + tg) =
            make_float4(e1[0], e1[1], e1[2], e1[3]);
    }
}

// ---------------------------------------------------------------------------
// Kernel 2: probability-domain forward scan, one warp per batch.
// ONLY change vs the proven scan: batched A/B half-ring refills (16 loads per
// batch -> one SB-slot group, consumed >= 16 steps later). Rescale every 16
// steps (proven cadence), select-based lane-0 kill (proven), select tail.
// ---------------------------------------------------------------------------
__device__ __forceinline__ void scan_rescale(float& q0, float& q1, float& q2,
                                             float& q3, int& kTot) {
    float s = fmaxf(fmaxf(q0, q1), fmaxf(q2, q3));
#pragma unroll
    for (int o = 16; o; o >>= 1)
        s = fmaxf(s, __shfl_xor_sync(0xffffffffu, s, o));
    if (s > 0.f) {
        int eb = (__float_as_int(s) >> 23) & 0xff;
        float sc = __int_as_float((254 - eb) << 23);
        q0 *= sc; q1 *= sc; q2 *= sc; q3 *= sc;
        kTot += eb - 127;
    }
}

__global__ __launch_bounds__(32)
void k_scan(const float* __restrict__ out_base,  // d_out (out[0]=loss, +1=lpm)
            const int* __restrict__ tlen,
            const int* __restrict__ mlen)
{
    const int b    = blockIdx.x;
    const int lane = threadIdx.x;
    const float4* __restrict__ Ev =
        (const float4*)(g_elp + (size_t)b * MM * TT);   // [m][32 lanes]

    const int mel_len = mlen[b];
    const int txt_len = tlen[b];
    const int last    = mel_len - 1;          // >= 255 for this dataset

    float q0 = (lane == 0) ? 1.f : 0.f;
    float q1 = 0.f, q2 = 0.f, q3 = 0.f;
    const bool isL0 = (lane == 0);
    const float L0 = out_base[1 + (size_t)b * TT * MM];  // lp[b,0,0]
    int kTot = 0;

#define STEPQ(e)                                                  \
    {                                                             \
        float top = __shfl_up_sync(0xffffffffu, q3, 1);           \
        if (isL0) top = 0.f;                                      \
        float n0 = (q0 + top) * (e).x;                            \
        float n1 = (q1 + q0)  * (e).y;                            \
        float n2 = (q2 + q1)  * (e).z;                            \
        float n3 = (q3 + q2)  * (e).w;                            \
        q0 = n0; q1 = n1; q2 = n2; q3 = n3;                       \
    }

#define STEPQ_PRED(e, act)                                        \
    {                                                             \
        float top = __shfl_up_sync(0xffffffffu, q3, 1);           \
        if (isL0) top = 0.f;                                      \
        float n0 = (q0 + top) * (e).x;                            \
        float n1 = (q1 + q0)  * (e).y;                            \
        float n2 = (q2 + q1)  * (e).z;                            \
        float n3 = (q3 + q2)  * (e).w;                            \
        q0 = (act) ? n0 : q0;                                     \
        q1 = (act) ? n1 : q1;                                     \
        q2 = (act) ? n2 : q2;                                     \
        q3 = (act) ? n3 : q3;                                     \
    }

    // Double-buffered half-rings: A holds m..m+15, B holds m+16..m+31.
    float4 A[16], Bf[16];
#pragma unroll
    for (int i = 0; i < 16; i++) A[i]  = Ev[(size_t)(1 + i) * 32 + lane];
#pragma unroll
    for (int i = 0; i < 16; i++) Bf[i] = Ev[(size_t)(17 + i) * 32 + lane];

    int m = 1;
    while (m + 31 <= last) {
        // consume A (steps m..m+15)
#pragma unroll
        for (int i = 0; i < 16; i++) STEPQ(A[i]);
        // batched refill A <- m+32..m+47 (clamped to valid region)
#pragma unroll
        for (int i = 0; i < 16; i++) {
            int mi = m + 32 + i; if (mi > MM - 1) mi = MM - 1;
            A[i] = Ev[(size_t)mi * 32 + lane];
        }
        scan_rescale(q0, q1, q2, q3, kTot);

        // consume B (steps m+16..m+31)
#pragma unroll
        for (int i = 0; i < 16; i++) STEPQ(Bf[i]);
        // batched refill B <- m+48..m+63 (clamped)
#pragma unroll
        for (int i = 0; i < 16; i++) {
            int mi = m + 48 + i; if (mi > MM - 1) mi = MM - 1;
            Bf[i] = Ev[(size_t)mi * 32 + lane];
        }
        scan_rescale(q0, q1, q2, q3, kTot);
        m += 32;
    }

    // tail: <= 31 remaining steps; rings hold m..m+31 (select-freeze, proven)
#pragma unroll
    for (int i = 0; i < 16; i++) STEPQ_PRED(A[i],  (m + i)      <= last);
#pragma unroll
    for (int i = 0; i < 16; i++) STEPQ_PRED(Bf[i], (m + 16 + i) <= last);

#undef STEPQ
#undef STEPQ_PRED

    // extract alpha_last, fold loss reduction
    {
        const int idx = txt_len - 1;
        const int sel = idx & 3;
        float v = (sel == 0) ? q0 : (sel == 1) ? q1 : (sel == 2) ? q2 : q3;
        v = __shfl_sync(0xffffffffu, v, idx >> 2);
        if (lane == 0) {
            float alpha = __logf(v) + (float)kTot * 0.69314718055994531f + L0;
            g_alpha[b] = alpha / (float)mel_len;
            __threadfence();
            unsigned ticket = atomicAdd(&g_cnt, 1u);
            if (ticket == BB - 1) {
                __threadfence();
                float s = 0.f;
#pragma unroll
                for (int i = 0; i < BB; i++)
                    s += ((volatile float*)g_alpha)[i];
                ((float*)out_base)[0] = -s * (1.f / BB);
                g_cnt = 0;   // reset for next graph replay
            }
        }
    }
}

// ---------------------------------------------------------------------------
extern "C" void kernel_launch(void* const* d_in, const int* in_sizes, int n_in,
                              void* d_out, int out_size)
{
    const float* ml  = (const float*)d_in[0];   // mu_logvar [16,128,160]
    const float* mel = (const float*)d_in[1];   // melspec   [16,80,512]
    const int*   tl  = (const int*)d_in[2];     // text_lengths [16]
    const int*   mll = (const int*)d_in[3];     // mel_lengths  [16]
    float* out = (float*)d_out;                 // [0]=loss, [1..]=log_prob_matrix

    cudaFuncSetAttribute(k_logprob,
                         cudaFuncAttributeMaxDynamicSharedMemorySize, SM_TOTAL);

    k_logprob<<<dim3(MM / MBLK, TT / TBLK, BB), K1_THREADS, SM_TOTAL>>>(
        ml, mel, out + 1);
    k_scan<<<BB, 32>>>(out, tl, mll);
}